// round 11
// baseline (speedup 1.0000x reference)
#include <cuda_runtime.h>
#include <cuda_bf16.h>
#include <cuda_fp16.h>
#include <math.h>

#define NN 50000
#define EE 800000
#define ET (EE + NN)
#define C0 256
#define H0 4
#define HD 64
#define C1 32
#define NEG 0.2f

#define ROWB 391            // 128-row blocks for gemm0
#define NA_RB 196           // row blocks in part A
#define NB_RB (ROWB - NA_RB)
#define HBLK 256            // hist blocks (fused in L1)
#define SCB 512             // scatter blocks (fused in L3)

// ---------------- device scratch (zero-initialized at load) ----------------
__device__ __half g_h0h[NN * C0];
__device__ __half g_hbh[NN * C0];
__device__ float g_as0[NN * H0];
__device__ float g_ad0[NN * H0];
__device__ float g_h1[NN * C1];
__device__ float g_as1[NN];
__device__ float g_ad1[NN];
__device__ float g_gsum[C1];
__device__ int g_cnt[NN];
__device__ int g_ptr[NN + 1];
__device__ int g_cur[NN];
__device__ unsigned g_done;
__device__ int g_csr_src[ET];

// ---------------- helpers ----------------
typedef unsigned long long u64t;
__device__ __forceinline__ u64t pack2(float lo, float hi) {
    u64t r; asm("mov.b64 %0, {%1, %2};" : "=l"(r) : "f"(lo), "f"(hi)); return r;
}
__device__ __forceinline__ void unpack2(u64t v, float& lo, float& hi) {
    asm("mov.b64 {%0, %1}, %2;" : "=f"(lo), "=f"(hi) : "l"(v));
}
__device__ __forceinline__ u64t fma2(u64t a, u64t b, u64t c) {
    u64t d; asm("fma.rn.f32x2 %0, %1, %2, %3;" : "=l"(d) : "l"(a), "l"(b), "l"(c)); return d;
}
__device__ __forceinline__ float tf32r(float f) {
    unsigned int u;
    asm("cvt.rna.tf32.f32 %0, %1;" : "=r"(u) : "f"(f));
    return __uint_as_float(u);
}
__device__ __forceinline__ void mma_tf32(float& d0, float& d1, float& d2, float& d3,
                                         unsigned a0, unsigned a1, unsigned a2, unsigned a3,
                                         unsigned b0, unsigned b1) {
    asm volatile("mma.sync.aligned.m16n8k8.row.col.f32.tf32.tf32.f32 "
                 "{%0,%1,%2,%3}, {%4,%5,%6,%7}, {%8,%9}, {%0,%1,%2,%3};"
                 : "+f"(d0), "+f"(d1), "+f"(d2), "+f"(d3)
                 : "r"(a0), "r"(a1), "r"(a2), "r"(a3), "r"(b0), "r"(b1));
}
__device__ __forceinline__ float leaky(float v) { return (v > 0.0f) ? v : NEG * v; }

// ---------------- gemm0 body: 128x128 tile (2 heads), warps 4x2, warp tile 32x64 ----------------
#define SA_S 20
#define SB_S 136
__device__ __forceinline__ void gemm0_body(int by, int hp,
                                           const float* __restrict__ A,
                                           const float* __restrict__ B,
                                           const float* __restrict__ a_src,
                                           const float* __restrict__ a_dst) {
    __shared__ float sA[128 * SA_S];
    __shared__ float sB[16 * SB_S];
    int tid = threadIdx.x;
    int wid = tid >> 5, lane = tid & 31;
    int gid = lane >> 2, tig = lane & 3;
    int warp_m = wid >> 1, warp_n = wid & 1;
    int head = hp * 2 + warp_n;
    int brow = by * 128, bcol = hp * 128;

    float acc[2][8][4];
    #pragma unroll
    for (int mt = 0; mt < 2; mt++)
        #pragma unroll
        for (int nt = 0; nt < 8; nt++)
            #pragma unroll
            for (int q = 0; q < 4; q++) acc[mt][nt][q] = 0.0f;

    for (int k0 = 0; k0 < 128; k0 += 16) {
        // A tile 128x16 transposed-ish into sA (row-major with stride SA_S)
        #pragma unroll
        for (int i = tid; i < 512; i += 256) {
            int r = i >> 2, cv = (i & 3) * 4;
            int gr = brow + r;
            float4 v = make_float4(0.f, 0.f, 0.f, 0.f);
            if (gr < NN) v = *(const float4*)(A + gr * 128 + k0 + cv);
            sA[r * SA_S + cv]     = tf32r(v.x);
            sA[r * SA_S + cv + 1] = tf32r(v.y);
            sA[r * SA_S + cv + 2] = tf32r(v.z);
            sA[r * SA_S + cv + 3] = tf32r(v.w);
        }
        // B tile 16x128
        #pragma unroll
        for (int i = tid; i < 512; i += 256) {
            int r = i >> 5, cv = (i & 31) * 4;
            float4 v = *(const float4*)(B + (k0 + r) * C0 + bcol + cv);
            sB[r * SB_S + cv]     = tf32r(v.x);
            sB[r * SB_S + cv + 1] = tf32r(v.y);
            sB[r * SB_S + cv + 2] = tf32r(v.z);
            sB[r * SB_S + cv + 3] = tf32r(v.w);
        }
        __syncthreads();
        #pragma unroll
        for (int ks = 0; ks < 16; ks += 8) {
            unsigned af[2][4];
            #pragma unroll
            for (int mt = 0; mt < 2; mt++) {
                int r0 = (warp_m * 32 + mt * 16 + gid) * SA_S;
                af[mt][0] = __float_as_uint(sA[r0 + ks + tig]);
                af[mt][1] = __float_as_uint(sA[r0 + 8 * SA_S + ks + tig]);
                af[mt][2] = __float_as_uint(sA[r0 + ks + tig + 4]);
                af[mt][3] = __float_as_uint(sA[r0 + 8 * SA_S + ks + tig + 4]);
            }
            #pragma unroll
            for (int nt = 0; nt < 8; nt++) {
                int col = warp_n * 64 + nt * 8 + gid;
                unsigned b0 = __float_as_uint(sB[(ks + tig) * SB_S + col]);
                unsigned b1 = __float_as_uint(sB[(ks + tig + 4) * SB_S + col]);
                #pragma unroll
                for (int mt = 0; mt < 2; mt++)
                    mma_tf32(acc[mt][nt][0], acc[mt][nt][1], acc[mt][nt][2], acc[mt][nt][3],
                             af[mt][0], af[mt][1], af[mt][2], af[mt][3], b0, b1);
            }
        }
        __syncthreads();
    }

    // epilogue: h0h fp16 store + per-warp alpha (warp owns rows x exactly one head)
    float asp[2][2] = {}, adp[2][2] = {};
    #pragma unroll
    for (int mt = 0; mt < 2; mt++) {
        int r0 = brow + warp_m * 32 + mt * 16 + gid;
        #pragma unroll
        for (int nt = 0; nt < 8; nt++) {
            int hcol = nt * 8 + tig * 2;
            float av0 = a_src[head * HD + hcol], av1 = a_src[head * HD + hcol + 1];
            float dv0 = a_dst[head * HD + hcol], dv1 = a_dst[head * HD + hcol + 1];
            float d0 = acc[mt][nt][0], d1 = acc[mt][nt][1];
            float d2 = acc[mt][nt][2], d3 = acc[mt][nt][3];
            asp[mt][0] += d0 * av0 + d1 * av1;
            asp[mt][1] += d2 * av0 + d3 * av1;
            adp[mt][0] += d0 * dv0 + d1 * dv1;
            adp[mt][1] += d2 * dv0 + d3 * dv1;
            int gcol = head * HD + hcol;
            if (r0 < NN)     *(__half2*)(g_h0h + (size_t)r0 * C0 + gcol)       = __floats2half2_rn(d0, d1);
            if (r0 + 8 < NN) *(__half2*)(g_h0h + (size_t)(r0 + 8) * C0 + gcol) = __floats2half2_rn(d2, d3);
        }
    }
    #pragma unroll
    for (int off = 1; off <= 2; off <<= 1) {
        #pragma unroll
        for (int mt = 0; mt < 2; mt++) {
            asp[mt][0] += __shfl_xor_sync(0xffffffffu, asp[mt][0], off);
            asp[mt][1] += __shfl_xor_sync(0xffffffffu, asp[mt][1], off);
            adp[mt][0] += __shfl_xor_sync(0xffffffffu, adp[mt][0], off);
            adp[mt][1] += __shfl_xor_sync(0xffffffffu, adp[mt][1], off);
        }
    }
    if (tig == 0) {
        #pragma unroll
        for (int mt = 0; mt < 2; mt++) {
            int r0 = brow + warp_m * 32 + mt * 16 + gid;
            if (r0 < NN)     { g_as0[r0 * H0 + head] = asp[mt][0];       g_ad0[r0 * H0 + head] = adp[mt][0]; }
            if (r0 + 8 < NN) { g_as0[(r0 + 8) * H0 + head] = asp[mt][1]; g_ad0[(r0 + 8) * H0 + head] = adp[mt][1]; }
        }
    }
}

// ---------------- L1: hist blocks + gemm0 part A ----------------
__global__ void gemm0a_hist_kernel(const float* __restrict__ A, const float* __restrict__ B,
                                   const float* __restrict__ a_src, const float* __restrict__ a_dst,
                                   const int* __restrict__ ei) {
    if (blockIdx.x < HBLK) {
        int tid = blockIdx.x * blockDim.x + threadIdx.x;
        int stride = HBLK * blockDim.x;
        for (int e = tid; e < EE; e += stride)
            atomicAdd(&g_cnt[ei[EE + e]], 1);
        return;
    }
    int g = blockIdx.x - HBLK;
    gemm0_body(g >> 1, g & 1, A, B, a_src, a_dst);
}

// ---------------- L2: scan (1 block, 1024 threads), warp-shuffle version ----------------
__global__ void scan_kernel() {
    __shared__ int wsum[32];
    int t = threadIdx.x;
    const int CH = (NN + 1023) / 1024;   // 49
    int base = t * CH;
    int cnts[CH];
    int local = 0;
    #pragma unroll 7
    for (int i = 0; i < CH; i++) {
        int idx = base + i;
        int c = 0;
        if (idx < NN) { c = g_cnt[idx] + 1; g_cnt[idx] = 0; }
        cnts[i] = c;
        local += c;
    }
    int lane = t & 31, wid = t >> 5;
    int v = local;
    #pragma unroll
    for (int off = 1; off < 32; off <<= 1) {
        int u = __shfl_up_sync(0xffffffffu, v, off);
        if (lane >= off) v += u;
    }
    if (lane == 31) wsum[wid] = v;
    __syncthreads();
    if (wid == 0) {
        int x = wsum[lane];
        #pragma unroll
        for (int off = 1; off < 32; off <<= 1) {
            int u = __shfl_up_sync(0xffffffffu, x, off);
            if (lane >= off) x += u;
        }
        wsum[lane] = x;
    }
    __syncthreads();
    int warpbase = (wid > 0) ? wsum[wid - 1] : 0;
    int run = warpbase + v - local;
    #pragma unroll 7
    for (int i = 0; i < CH; i++) {
        int idx = base + i;
        if (idx < NN) {
            g_ptr[idx] = run;
            g_cur[idx] = run;
            run += cnts[i];
        }
    }
    if (t == 1023) g_ptr[NN] = run;
}

// ---------------- L3: gemm0 part B + scatter blocks ----------------
__global__ void gemm0b_scatter_kernel(const float* __restrict__ A, const float* __restrict__ B,
                                      const float* __restrict__ a_src, const float* __restrict__ a_dst,
                                      const int* __restrict__ ei) {
    if (blockIdx.x < NB_RB * 2) {
        int g = blockIdx.x;
        gemm0_body(NA_RB + (g >> 1), g & 1, A, B, a_src, a_dst);
        return;
    }
    int tid = (blockIdx.x - NB_RB * 2) * blockDim.x + threadIdx.x;
    int stride = SCB * blockDim.x;
    for (int e = tid; e < ET; e += stride) {
        int s, d;
        if (e < EE) { s = ei[e]; d = ei[EE + e]; }
        else        { s = e - EE; d = s; }
        int pos = atomicAdd(&g_cur[d], 1);
        g_csr_src[pos] = s;
    }
}

// ---------------- L4: agg0 — batched exp (chunk 8) + f32x2 accumulate + BN + ReLU ----------------
__global__ void agg0_csr(const float* __restrict__ b0,
                         const float* __restrict__ bn_g, const float* __restrict__ bn_b,
                         const float* __restrict__ bn_m, const float* __restrict__ bn_v) {
    int n = (blockIdx.x * blockDim.x + threadIdx.x) >> 5;
    if (n >= NN) return;
    int lane = threadIdx.x & 31;
    int hc = lane >> 3;                  // head for this lane's 8 cols
    int beg = g_ptr[n], end = g_ptr[n + 1];
    float ad = g_ad0[n * H0 + hc];

    float den = 0.0f;
    u64t ac01 = 0, ac23 = 0, ac45 = 0, ac67 = 0;

    for (int i0 = beg; i0 < end; i0 += 8) {
        // batch: lane (hc, sub) computes exp for edge i0+sub, head hc
        int e = i0 + (lane & 7);
        bool valid = e < end;
        int s = g_csr_src[valid ? e : beg];
        float t = leaky(g_as0[s * H0 + hc] + ad);
        float w = valid ? __expf(t) : 0.0f;
        den += w;
        int cnt = min(8, end - i0);       // warp-uniform
        #pragma unroll 4
        for (int j = 0; j < cnt; j++) {
            float wj = __shfl_sync(0xffffffffu, w, hc * 8 + j);
            int   sj = __shfl_sync(0xffffffffu, s, hc * 8 + j);
            uint4 hv = *(const uint4*)(g_h0h + (size_t)sj * C0 + lane * 8);
            const __half2* hp = (const __half2*)&hv;
            float2 f0 = __half22float2(hp[0]);
            float2 f1 = __half22float2(hp[1]);
            float2 f2 = __half22float2(hp[2]);
            float2 f3 = __half22float2(hp[3]);
            u64t wd = pack2(wj, wj);
            ac01 = fma2(pack2(f0.x, f0.y), wd, ac01);
            ac23 = fma2(pack2(f1.x, f1.y), wd, ac23);
            ac45 = fma2(pack2(f2.x, f2.y), wd, ac45);
            ac67 = fma2(pack2(f3.x, f3.y), wd, ac67);
        }
    }
    // den: sum partial over the 8 sub-lanes of this head group
    den += __shfl_xor_sync(0xffffffffu, den, 1);
    den += __shfl_xor_sync(0xffffffffu, den, 2);
    den += __shfl_xor_sync(0xffffffffu, den, 4);
    float inv = 1.0f / den;

    float a0, a1, a2, a3, a4, a5, a6, a7;
    unpack2(ac01, a0, a1); unpack2(ac23, a2, a3);
    unpack2(ac45, a4, a5); unpack2(ac67, a6, a7);

    int c = lane * 8;
    float4 bL = *(const float4*)(b0 + c),   bH = *(const float4*)(b0 + c + 4);
    float4 gL = *(const float4*)(bn_g + c), gH = *(const float4*)(bn_g + c + 4);
    float4 tL = *(const float4*)(bn_b + c), tH = *(const float4*)(bn_b + c + 4);
    float4 mL = *(const float4*)(bn_m + c), mH = *(const float4*)(bn_m + c + 4);
    float4 vL = *(const float4*)(bn_v + c), vH = *(const float4*)(bn_v + c + 4);
    float o0 = fmaxf((a0 * inv + bL.x - mL.x) * (gL.x * rsqrtf(vL.x + 1e-5f)) + tL.x, 0.0f);
    float o1 = fmaxf((a1 * inv + bL.y - mL.y) * (gL.y * rsqrtf(vL.y + 1e-5f)) + tL.y, 0.0f);
    float o2 = fmaxf((a2 * inv + bL.z - mL.z) * (gL.z * rsqrtf(vL.z + 1e-5f)) + tL.z, 0.0f);
    float o3 = fmaxf((a3 * inv + bL.w - mL.w) * (gL.w * rsqrtf(vL.w + 1e-5f)) + tL.w, 0.0f);
    float o4 = fmaxf((a4 * inv + bH.x - mH.x) * (gH.x * rsqrtf(vH.x + 1e-5f)) + tH.x, 0.0f);
    float o5 = fmaxf((a5 * inv + bH.y - mH.y) * (gH.y * rsqrtf(vH.y + 1e-5f)) + tH.y, 0.0f);
    float o6 = fmaxf((a6 * inv + bH.z - mH.z) * (gH.z * rsqrtf(vH.z + 1e-5f)) + tH.z, 0.0f);
    float o7 = fmaxf((a7 * inv + bH.w - mH.w) * (gH.w * rsqrtf(vH.w + 1e-5f)) + tH.w, 0.0f);

    uint4 outv;
    __half2* op = (__half2*)&outv;
    op[0] = __floats2half2_rn(o0, o1);
    op[1] = __floats2half2_rn(o2, o3);
    op[2] = __floats2half2_rn(o4, o5);
    op[3] = __floats2half2_rn(o6, o7);
    *(uint4*)(g_hbh + (size_t)n * C0 + c) = outv;
}

// ---------------- L5: gemm1 (fp16 A, tf32 mma) + fused alpha1 ----------------
#define SB1_S 40
__global__ void gemm1_kernel(const float* __restrict__ B,
                             const float* __restrict__ a_src, const float* __restrict__ a_dst) {
    __shared__ float sA[128 * SA_S];
    __shared__ float sB[16 * SB1_S];
    int tid = threadIdx.x;
    int wid = tid >> 5, lane = tid & 31;
    int gid = lane >> 2, tig = lane & 3;
    int brow = blockIdx.y * 128;

    float acc[4][4];
    #pragma unroll
    for (int nt = 0; nt < 4; nt++)
        #pragma unroll
        for (int q = 0; q < 4; q++) acc[nt][q] = 0.0f;

    for (int k0 = 0; k0 < 256; k0 += 16) {
        {
            int i = tid;
            int r = i >> 1, c8 = (i & 1) * 8;
            int gr = brow + r;
            uint4 hv = make_uint4(0, 0, 0, 0);
            if (gr < NN) hv = *(const uint4*)(g_hbh + (size_t)gr * C0 + k0 + c8);
            const __half2* hp = (const __half2*)&hv;
            float2 f0 = __half22float2(hp[0]);
            float2 f1 = __half22float2(hp[1]);
            float2 f2 = __half22float2(hp[2]);
            float2 f3 = __half22float2(hp[3]);
            sA[r * SA_S + c8]     = f0.x;
            sA[r * SA_S + c8 + 1] = f0.y;
            sA[r * SA_S + c8 + 2] = f1.x;
            sA[r * SA_S + c8 + 3] = f1.y;
            sA[r * SA_S + c8 + 4] = f2.x;
            sA[r * SA_S + c8 + 5] = f2.y;
            sA[r * SA_S + c8 + 6] = f3.x;
            sA[r * SA_S + c8 + 7] = f3.y;
        }
        if (tid < 128) {
            int r = tid >> 3, cq = (tid & 7) * 4;
            float4 v = *(const float4*)(B + (k0 + r) * C1 + cq);
            sB[r * SB1_S + cq]     = tf32r(v.x);
            sB[r * SB1_S + cq + 1] = tf32r(v.y);
            sB[r * SB1_S + cq + 2] = tf32r(v.z);
            sB[r * SB1_S + cq + 3] = tf32r(v.w);
        }
        __syncthreads();
        #pragma unroll
        for (int ks = 0; ks < 16; ks += 8) {
            int r0 = (wid * 16 + gid) * SA_S;
            unsigned a0 = __float_as_uint(sA[r0 + ks + tig]);
            unsigned a1 = __float_as_uint(sA[r0 + 8 * SA_S + ks + tig]);
            unsigned a2 = __float_as_uint(sA[r0 + ks + tig + 4]);
            unsigned a3 = __float_as_uint(sA[r0 + 8 * SA_S + ks + tig + 4]);
            #pragma unroll
            for (int nt = 0; nt < 4; nt++) {
                int col = nt * 8 + gid;
                unsigned b0 = __float_as_uint(sB[(ks + tig) * SB1_S + col]);
                unsigned b1 = __float_as_uint(sB[(ks + tig + 4) * SB1_S + col]);
                mma_tf32(acc[nt][0], acc[nt][1], acc[nt][2], acc[nt][3],
                         a0, a1, a2, a3, b0, b1);
            }
        }
        __syncthreads();
    }

    int r0 = brow + wid * 16 + gid;
    float as0 = 0, as1 = 0, ad0 = 0, ad1 = 0;
    #pragma unroll
    for (int nt = 0; nt < 4; nt++) {
        int col = nt * 8 + tig * 2;
        float av0 = a_src[col], av1 = a_src[col + 1];
        float dv0 = a_dst[col], dv1 = a_dst[col + 1];
        float d0 = acc[nt][0], d1 = acc[nt][1], d2 = acc[nt][2], d3 = acc[nt][3];
        as0 += d0 * av0 + d1 * av1;
        as1 += d2 * av0 + d3 * av1;
        ad0 += d0 * dv0 + d1 * dv1;
        ad1 += d2 * dv0 + d3 * dv1;
        if (r0 < NN)     *(float2*)(g_h1 + r0 * C1 + col)       = make_float2(d0, d1);
        if (r0 + 8 < NN) *(float2*)(g_h1 + (r0 + 8) * C1 + col) = make_float2(d2, d3);
    }
    #pragma unroll
    for (int off = 1; off <= 2; off <<= 1) {
        as0 += __shfl_xor_sync(0xffffffffu, as0, off);
        as1 += __shfl_xor_sync(0xffffffffu, as1, off);
        ad0 += __shfl_xor_sync(0xffffffffu, ad0, off);
        ad1 += __shfl_xor_sync(0xffffffffu, ad1, off);
    }
    if (tig == 0) {
        if (r0 < NN)     { g_as1[r0] = as0;     g_ad1[r0] = ad0; }
        if (r0 + 8 < NN) { g_as1[r0 + 8] = as1; g_ad1[r0 + 8] = ad1; }
    }
}

// ---------------- L6: agg1 (batched exp, chunk 32) + b1 + colsum + fused predict ----------------
__global__ void agg1_pred(float* __restrict__ emb, const float* __restrict__ b1,
                          const float* __restrict__ hW1, const float* __restrict__ hb1,
                          const float* __restrict__ hW2, const float* __restrict__ hb2,
                          float* __restrict__ out, int pred_idx) {
    __shared__ float sred[256];
    __shared__ unsigned s_ticket;
    int tid = threadIdx.x;
    int n = (blockIdx.x * blockDim.x + tid) >> 5;
    int lane = tid & 31;
    int beg = g_ptr[n], end = g_ptr[n + 1];
    float adn = g_ad1[n];

    float den = 0.0f, acc = 0.0f;
    for (int i0 = beg; i0 < end; i0 += 32) {
        int e = i0 + lane;
        bool valid = e < end;
        int s = g_csr_src[valid ? e : beg];
        float t = leaky(g_as1[s] + adn);
        float w = valid ? __expf(t) : 0.0f;
        den += w;
        int cnt = min(32, end - i0);      // warp-uniform
        #pragma unroll 4
        for (int j = 0; j < cnt; j++) {
            float wj = __shfl_sync(0xffffffffu, w, j);
            int   sj = __shfl_sync(0xffffffffu, s, j);
            acc += wj * g_h1[sj * C1 + lane];
        }
    }
    #pragma unroll
    for (int off = 16; off >= 1; off >>= 1)
        den += __shfl_xor_sync(0xffffffffu, den, off);

    float val = acc / den + b1[lane];
    emb[n * C1 + lane] = val;

    sred[tid] = val;
    __syncthreads();
    if (tid < 32) {
        float t = sred[tid];
        #pragma unroll
        for (int r = 1; r < 8; r++) t += sred[r * 32 + tid];
        atomicAdd(&g_gsum[tid], t);
    }
    __threadfence();
    if (tid == 0) s_ticket = atomicAdd(&g_done, 1u);
    __syncthreads();
    if (s_ticket != gridDim.x - 1) return;

    __shared__ float ge[C1];
    __shared__ float red[64];
    if (tid < C1) ge[tid] = g_gsum[tid] * (1.0f / (float)NN);
    __syncthreads();
    if (tid < 64) {
        float s = hb1[tid];
        #pragma unroll
        for (int c = 0; c < C1; c++) s += ge[c] * hW1[c * 64 + tid];
        red[tid] = fmaxf(s, 0.0f) * hW2[tid];
    }
    __syncthreads();
    if (tid == 0) {
        float t = 0.0f;
        #pragma unroll
        for (int i = 0; i < 64; i++) t += red[i];
        out[pred_idx] = t + hb2[0];
        g_done = 0;
    }
    if (tid < C1) g_gsum[tid] = 0.0f;
}

// ---------------- launch ----------------
extern "C" void kernel_launch(void* const* d_in, const int* in_sizes, int n_in,
                              void* d_out, int out_size) {
    const float* x       = (const float*)d_in[0];
    const int*   ei      = (const int*)d_in[1];
    const float* W0      = (const float*)d_in[2];
    const float* a_src0  = (const float*)d_in[3];
    const float* a_dst0  = (const float*)d_in[4];
    const float* b0      = (const float*)d_in[5];
    const float* bn_g    = (const float*)d_in[6];
    const float* bn_b    = (const float*)d_in[7];
    const float* bn_m    = (const float*)d_in[8];
    const float* bn_v    = (const float*)d_in[9];
    const float* W1      = (const float*)d_in[10];
    const float* a_src1  = (const float*)d_in[11];
    const float* a_dst1  = (const float*)d_in[12];
    const float* b1      = (const float*)d_in[13];
    const float* hW1     = (const float*)d_in[14];
    const float* hb1     = (const float*)d_in[15];
    const float* hW2     = (const float*)d_in[16];
    const float* hb2     = (const float*)d_in[17];
    float* out = (float*)d_out;

    gemm0a_hist_kernel<<<HBLK + NA_RB * 2, 256>>>(x, W0, a_src0, a_dst0, ei);
    scan_kernel<<<1, 1024>>>();
    gemm0b_scatter_kernel<<<NB_RB * 2 + SCB, 256>>>(x, W0, a_src0, a_dst0, ei);
    agg0_csr<<<(NN * 32 + 255) / 256, 256>>>(b0, bn_g, bn_b, bn_m, bn_v);
    {
        dim3 grid(1, (NN + 127) / 128);
        gemm1_kernel<<<grid, 256>>>(W1, a_src1, a_dst1);
    }
    agg1_pred<<<(NN + 7) / 8, 256>>>(out, b1, hW1, hb1, hW2, hb2, out, out_size - 1);
}

// round 12
// speedup vs baseline: 1.0333x; 1.0333x over previous
#include <cuda_runtime.h>
#include <cuda_bf16.h>
#include <cuda_fp16.h>
#include <math.h>

#define NN 50000
#define EE 800000
#define ET (EE + NN)
#define C0 256
#define H0 4
#define HD 64
#define C1 32
#define NEG 0.2f

#define ROWB 391            // total 128-row blocks for gemm0
#define NA 196              // row blocks in part A
#define NB (ROWB - NA)      // row blocks in part B
#define HBLK 256            // hist blocks (fused in part A launch)
#define SCB 512             // scatter blocks (fused in part B launch)

// ---------------- device scratch (zero-initialized at load) ----------------
__device__ __half g_h0h[NN * C0];
__device__ __half g_hbh[NN * C0];
__device__ float g_as0[NN * H0];
__device__ float g_ad0[NN * H0];
__device__ float g_h1[NN * C1];
__device__ float g_as1[NN];
__device__ float g_ad1[NN];
__device__ float g_gsum[C1];          // zeroed by last agg1 block each run
__device__ int g_cnt[NN];             // zeroed by scan each run
__device__ int g_ptr[NN + 1];
__device__ int g_cur[NN];
__device__ unsigned g_done;           // zeroed by last agg1 block each run
__device__ int g_csr_src[ET];

// ---------------- helpers ----------------
typedef unsigned long long u64t;
__device__ __forceinline__ u64t pack2(float lo, float hi) {
    u64t r; asm("mov.b64 %0, {%1, %2};" : "=l"(r) : "f"(lo), "f"(hi)); return r;
}
__device__ __forceinline__ void unpack2(u64t v, float& lo, float& hi) {
    asm("mov.b64 {%0, %1}, %2;" : "=f"(lo), "=f"(hi) : "l"(v));
}
__device__ __forceinline__ u64t fma2(u64t a, u64t b, u64t c) {
    u64t d; asm("fma.rn.f32x2 %0, %1, %2, %3;" : "=l"(d) : "l"(a), "l"(b), "l"(c)); return d;
}
__device__ __forceinline__ float tf32r(float f) {
    unsigned int u;
    asm("cvt.rna.tf32.f32 %0, %1;" : "=r"(u) : "f"(f));
    return __uint_as_float(u);
}
__device__ __forceinline__ void mma_tf32(float& d0, float& d1, float& d2, float& d3,
                                         unsigned a0, unsigned a1, unsigned a2, unsigned a3,
                                         unsigned b0, unsigned b1) {
    asm volatile("mma.sync.aligned.m16n8k8.row.col.f32.tf32.tf32.f32 "
                 "{%0,%1,%2,%3}, {%4,%5,%6,%7}, {%8,%9}, {%0,%1,%2,%3};"
                 : "+f"(d0), "+f"(d1), "+f"(d2), "+f"(d3)
                 : "r"(a0), "r"(a1), "r"(a2), "r"(a3), "r"(b0), "r"(b1));
}

__device__ __forceinline__ float leaky(float v) { return (v > 0.0f) ? v : NEG * v; }

// ---------------- gemm0 body: 128x64 tile (one head), warps 4x2, BK=16 ----------------
#define SA_S 20
#define SB_S 72
__device__ __forceinline__ void gemm0_body(int by, int head,
                                           const float* __restrict__ A,
                                           const float* __restrict__ B,
                                           const float* __restrict__ a_src,
                                           const float* __restrict__ a_dst) {
    __shared__ float sA[128 * SA_S];
    __shared__ float sB[16 * SB_S];
    __shared__ float s_as[128], s_ad[128];
    int tid = threadIdx.x;
    int wid = tid >> 5, lane = tid & 31;
    int gid = lane >> 2, tig = lane & 3;
    int warp_m = wid >> 1, warp_n = wid & 1;
    int brow = by * 128, bcol = head * 64;

    float acc[2][4][4];
    #pragma unroll
    for (int mt = 0; mt < 2; mt++)
        #pragma unroll
        for (int nt = 0; nt < 4; nt++)
            #pragma unroll
            for (int q = 0; q < 4; q++) acc[mt][nt][q] = 0.0f;

    for (int k0 = 0; k0 < 128; k0 += 16) {
        #pragma unroll
        for (int i = tid; i < 128 * 4; i += 256) {
            int r = i >> 2, cq = (i & 3) * 4;
            int gr = brow + r;
            float4 v = make_float4(0.f, 0.f, 0.f, 0.f);
            if (gr < NN) v = *(const float4*)(A + gr * 128 + k0 + cq);
            sA[r * SA_S + cq]     = tf32r(v.x);
            sA[r * SA_S + cq + 1] = tf32r(v.y);
            sA[r * SA_S + cq + 2] = tf32r(v.z);
            sA[r * SA_S + cq + 3] = tf32r(v.w);
        }
        #pragma unroll
        for (int i = tid; i < 16 * 16; i += 256) {
            int r = i >> 4, cq = (i & 15) * 4;
            float4 v = *(const float4*)(B + (k0 + r) * C0 + bcol + cq);
            sB[r * SB_S + cq]     = tf32r(v.x);
            sB[r * SB_S + cq + 1] = tf32r(v.y);
            sB[r * SB_S + cq + 2] = tf32r(v.z);
            sB[r * SB_S + cq + 3] = tf32r(v.w);
        }
        __syncthreads();
        #pragma unroll
        for (int ks = 0; ks < 16; ks += 8) {
            unsigned af[2][4];
            #pragma unroll
            for (int mt = 0; mt < 2; mt++) {
                int r0 = (warp_m * 32 + mt * 16 + gid) * SA_S;
                af[mt][0] = __float_as_uint(sA[r0 + ks + tig]);
                af[mt][1] = __float_as_uint(sA[r0 + 8 * SA_S + ks + tig]);
                af[mt][2] = __float_as_uint(sA[r0 + ks + tig + 4]);
                af[mt][3] = __float_as_uint(sA[r0 + 8 * SA_S + ks + tig + 4]);
            }
            unsigned bf[4][2];
            #pragma unroll
            for (int nt = 0; nt < 4; nt++) {
                int col = warp_n * 32 + nt * 8 + gid;
                bf[nt][0] = __float_as_uint(sB[(ks + tig) * SB_S + col]);
                bf[nt][1] = __float_as_uint(sB[(ks + tig + 4) * SB_S + col]);
            }
            #pragma unroll
            for (int mt = 0; mt < 2; mt++)
                #pragma unroll
                for (int nt = 0; nt < 4; nt++)
                    mma_tf32(acc[mt][nt][0], acc[mt][nt][1], acc[mt][nt][2], acc[mt][nt][3],
                             af[mt][0], af[mt][1], af[mt][2], af[mt][3],
                             bf[nt][0], bf[nt][1]);
        }
        __syncthreads();
    }

    if (tid < 128) { s_as[tid] = 0.0f; s_ad[tid] = 0.0f; }
    __syncthreads();

    float asp[2][2] = {}, adp[2][2] = {};
    #pragma unroll
    for (int mt = 0; mt < 2; mt++) {
        int r0 = brow + warp_m * 32 + mt * 16 + gid;
        #pragma unroll
        for (int nt = 0; nt < 4; nt++) {
            int hcol = warp_n * 32 + nt * 8 + tig * 2;
            float av0 = a_src[head * HD + hcol],  av1 = a_src[head * HD + hcol + 1];
            float dv0 = a_dst[head * HD + hcol],  dv1 = a_dst[head * HD + hcol + 1];
            float d0 = acc[mt][nt][0], d1 = acc[mt][nt][1];
            float d2 = acc[mt][nt][2], d3 = acc[mt][nt][3];
            asp[mt][0] += d0 * av0 + d1 * av1;
            asp[mt][1] += d2 * av0 + d3 * av1;
            adp[mt][0] += d0 * dv0 + d1 * dv1;
            adp[mt][1] += d2 * dv0 + d3 * dv1;
            int col = bcol + hcol;
            if (r0 < NN)     *(__half2*)(g_h0h + (size_t)r0 * C0 + col)       = __floats2half2_rn(d0, d1);
            if (r0 + 8 < NN) *(__half2*)(g_h0h + (size_t)(r0 + 8) * C0 + col) = __floats2half2_rn(d2, d3);
        }
    }
    #pragma unroll
    for (int off = 1; off <= 2; off <<= 1) {
        #pragma unroll
        for (int mt = 0; mt < 2; mt++) {
            asp[mt][0] += __shfl_xor_sync(0xffffffffu, asp[mt][0], off);
            asp[mt][1] += __shfl_xor_sync(0xffffffffu, asp[mt][1], off);
            adp[mt][0] += __shfl_xor_sync(0xffffffffu, adp[mt][0], off);
            adp[mt][1] += __shfl_xor_sync(0xffffffffu, adp[mt][1], off);
        }
    }
    if (tig == 0) {
        #pragma unroll
        for (int mt = 0; mt < 2; mt++) {
            int lr = warp_m * 32 + mt * 16 + gid;
            atomicAdd(&s_as[lr], asp[mt][0]);
            atomicAdd(&s_as[lr + 8], asp[mt][1]);
            atomicAdd(&s_ad[lr], adp[mt][0]);
            atomicAdd(&s_ad[lr + 8], adp[mt][1]);
        }
    }
    __syncthreads();
    if (tid < 128) {
        int gr = brow + tid;
        if (gr < NN) {
            g_as0[gr * H0 + head] = s_as[tid];
            g_ad0[gr * H0 + head] = s_ad[tid];
        }
    }
}

// ---------------- L1: hist blocks + gemm0 part A ----------------
__global__ void gemm0a_hist_kernel(const float* __restrict__ A, const float* __restrict__ B,
                                   const float* __restrict__ a_src, const float* __restrict__ a_dst,
                                   const int* __restrict__ ei) {
    if (blockIdx.x < HBLK) {
        int tid = blockIdx.x * blockDim.x + threadIdx.x;
        int stride = HBLK * blockDim.x;
        for (int e = tid; e < EE; e += stride)
            atomicAdd(&g_cnt[ei[EE + e]], 1);
        return;
    }
    int g = blockIdx.x - HBLK;
    gemm0_body(g >> 2, g & 3, A, B, a_src, a_dst);
}

// ---------------- L2: scan (1 block, 1024 threads), warp-shuffle version ----------------
__global__ void scan_kernel() {
    __shared__ int wsum[32];
    int t = threadIdx.x;
    const int CH = (NN + 1023) / 1024;   // 49
    int base = t * CH;
    int cnts[CH];
    int local = 0;
    #pragma unroll 7
    for (int i = 0; i < CH; i++) {
        int idx = base + i;
        int c = 0;
        if (idx < NN) { c = g_cnt[idx] + 1; g_cnt[idx] = 0; }   // +1 self loop; reset for next run
        cnts[i] = c;
        local += c;
    }
    int lane = t & 31, wid = t >> 5;
    int v = local;
    #pragma unroll
    for (int off = 1; off < 32; off <<= 1) {
        int u = __shfl_up_sync(0xffffffffu, v, off);
        if (lane >= off) v += u;
    }
    if (lane == 31) wsum[wid] = v;
    __syncthreads();
    if (wid == 0) {
        int x = wsum[lane];
        #pragma unroll
        for (int off = 1; off < 32; off <<= 1) {
            int u = __shfl_up_sync(0xffffffffu, x, off);
            if (lane >= off) x += u;
        }
        wsum[lane] = x;
    }
    __syncthreads();
    int warpbase = (wid > 0) ? wsum[wid - 1] : 0;
    int run = warpbase + v - local;
    #pragma unroll 7
    for (int i = 0; i < CH; i++) {
        int idx = base + i;
        if (idx < NN) {
            g_ptr[idx] = run;
            g_cur[idx] = run;
            run += cnts[i];
        }
    }
    if (t == 1023) g_ptr[NN] = run;
}

// ---------------- L3: gemm0 part B + scatter blocks ----------------
__global__ void gemm0b_scatter_kernel(const float* __restrict__ A, const float* __restrict__ B,
                                      const float* __restrict__ a_src, const float* __restrict__ a_dst,
                                      const int* __restrict__ ei) {
    if (blockIdx.x < NB * 4) {
        int g = blockIdx.x;
        gemm0_body(NA + (g >> 2), g & 3, A, B, a_src, a_dst);
        return;
    }
    int tid = (blockIdx.x - NB * 4) * blockDim.x + threadIdx.x;
    int stride = SCB * blockDim.x;
    for (int e = tid; e < ET; e += stride) {
        int s, d;
        if (e < EE) { s = ei[e]; d = ei[EE + e]; }
        else        { s = e - EE; d = s; }
        int pos = atomicAdd(&g_cur[d], 1);
        g_csr_src[pos] = s;
    }
}

// ---------------- L4: agg0 (CSR softmax no-max + aggregate + BN + ReLU), f32x2 accumulate ----------------
__global__ void agg0_csr(const float* __restrict__ b0,
                         const float* __restrict__ bn_g, const float* __restrict__ bn_b,
                         const float* __restrict__ bn_m, const float* __restrict__ bn_v) {
    int n = (blockIdx.x * blockDim.x + threadIdx.x) >> 5;
    if (n >= NN) return;
    int lane = threadIdx.x & 31;
    int hc = lane >> 3;
    int beg = g_ptr[n], end = g_ptr[n + 1];
    float ad = g_ad0[n * H0 + hc];

    float den = 0.0f;
    u64t ac01 = 0, ac23 = 0, ac45 = 0, ac67 = 0;
    for (int i = beg; i < end; i++) {
        int s = g_csr_src[i];
        float e = leaky(g_as0[s * H0 + hc] + ad);
        float w = __expf(e);          // one warp MUFU; per-lane redundancy is free
        den += w;
        uint4 hv = *(const uint4*)(g_h0h + (size_t)s * C0 + lane * 8);
        const __half2* hp = (const __half2*)&hv;
        float2 f0 = __half22float2(hp[0]);
        float2 f1 = __half22float2(hp[1]);
        float2 f2 = __half22float2(hp[2]);
        float2 f3 = __half22float2(hp[3]);
        u64t wd = pack2(w, w);
        ac01 = fma2(pack2(f0.x, f0.y), wd, ac01);
        ac23 = fma2(pack2(f1.x, f1.y), wd, ac23);
        ac45 = fma2(pack2(f2.x, f2.y), wd, ac45);
        ac67 = fma2(pack2(f3.x, f3.y), wd, ac67);
    }
    float inv = 1.0f / den;

    float a0, a1, a2, a3, a4, a5, a6, a7;
    unpack2(ac01, a0, a1); unpack2(ac23, a2, a3);
    unpack2(ac45, a4, a5); unpack2(ac67, a6, a7);

    int c = lane * 8;
    float4 bL = *(const float4*)(b0 + c),   bH = *(const float4*)(b0 + c + 4);
    float4 gL = *(const float4*)(bn_g + c), gH = *(const float4*)(bn_g + c + 4);
    float4 tL = *(const float4*)(bn_b + c), tH = *(const float4*)(bn_b + c + 4);
    float4 mL = *(const float4*)(bn_m + c), mH = *(const float4*)(bn_m + c + 4);
    float4 vL = *(const float4*)(bn_v + c), vH = *(const float4*)(bn_v + c + 4);
    float o0 = fmaxf((a0 * inv + bL.x - mL.x) * (gL.x * rsqrtf(vL.x + 1e-5f)) + tL.x, 0.0f);
    float o1 = fmaxf((a1 * inv + bL.y - mL.y) * (gL.y * rsqrtf(vL.y + 1e-5f)) + tL.y, 0.0f);
    float o2 = fmaxf((a2 * inv + bL.z - mL.z) * (gL.z * rsqrtf(vL.z + 1e-5f)) + tL.z, 0.0f);
    float o3 = fmaxf((a3 * inv + bL.w - mL.w) * (gL.w * rsqrtf(vL.w + 1e-5f)) + tL.w, 0.0f);
    float o4 = fmaxf((a4 * inv + bH.x - mH.x) * (gH.x * rsqrtf(vH.x + 1e-5f)) + tH.x, 0.0f);
    float o5 = fmaxf((a5 * inv + bH.y - mH.y) * (gH.y * rsqrtf(vH.y + 1e-5f)) + tH.y, 0.0f);
    float o6 = fmaxf((a6 * inv + bH.z - mH.z) * (gH.z * rsqrtf(vH.z + 1e-5f)) + tH.z, 0.0f);
    float o7 = fmaxf((a7 * inv + bH.w - mH.w) * (gH.w * rsqrtf(vH.w + 1e-5f)) + tH.w, 0.0f);

    uint4 outv;
    __half2* op = (__half2*)&outv;
    op[0] = __floats2half2_rn(o0, o1);
    op[1] = __floats2half2_rn(o2, o3);
    op[2] = __floats2half2_rn(o4, o5);
    op[3] = __floats2half2_rn(o6, o7);
    *(uint4*)(g_hbh + (size_t)n * C0 + c) = outv;
}

// ---------------- L5: gemm1 (fp16 A, tf32 mma) + fused alpha1 ----------------
#define SB1_S 40
__global__ void gemm1_kernel(const float* __restrict__ B,
                             const float* __restrict__ a_src, const float* __restrict__ a_dst) {
    __shared__ float sA[128 * SA_S];
    __shared__ float sB[16 * SB1_S];
    int tid = threadIdx.x;
    int wid = tid >> 5, lane = tid & 31;
    int gid = lane >> 2, tig = lane & 3;
    int brow = blockIdx.y * 128;

    float acc[4][4];
    #pragma unroll
    for (int nt = 0; nt < 4; nt++)
        #pragma unroll
        for (int q = 0; q < 4; q++) acc[nt][q] = 0.0f;

    for (int k0 = 0; k0 < 256; k0 += 16) {
        {
            int i = tid;
            int r = i >> 1, c8 = (i & 1) * 8;
            int gr = brow + r;
            uint4 hv = make_uint4(0, 0, 0, 0);
            if (gr < NN) hv = *(const uint4*)(g_hbh + (size_t)gr * C0 + k0 + c8);
            const __half2* hp = (const __half2*)&hv;
            float2 f0 = __half22float2(hp[0]);
            float2 f1 = __half22float2(hp[1]);
            float2 f2 = __half22float2(hp[2]);
            float2 f3 = __half22float2(hp[3]);
            sA[r * SA_S + c8]     = f0.x;
            sA[r * SA_S + c8 + 1] = f0.y;
            sA[r * SA_S + c8 + 2] = f1.x;
            sA[r * SA_S + c8 + 3] = f1.y;
            sA[r * SA_S + c8 + 4] = f2.x;
            sA[r * SA_S + c8 + 5] = f2.y;
            sA[r * SA_S + c8 + 6] = f3.x;
            sA[r * SA_S + c8 + 7] = f3.y;
        }
        if (tid < 128) {
            int r = tid >> 3, cq = (tid & 7) * 4;
            float4 v = *(const float4*)(B + (k0 + r) * C1 + cq);
            sB[r * SB1_S + cq]     = tf32r(v.x);
            sB[r * SB1_S + cq + 1] = tf32r(v.y);
            sB[r * SB1_S + cq + 2] = tf32r(v.z);
            sB[r * SB1_S + cq + 3] = tf32r(v.w);
        }
        __syncthreads();
        #pragma unroll
        for (int ks = 0; ks < 16; ks += 8) {
            int r0 = (wid * 16 + gid) * SA_S;
            unsigned a0 = __float_as_uint(sA[r0 + ks + tig]);
            unsigned a1 = __float_as_uint(sA[r0 + 8 * SA_S + ks + tig]);
            unsigned a2 = __float_as_uint(sA[r0 + ks + tig + 4]);
            unsigned a3 = __float_as_uint(sA[r0 + 8 * SA_S + ks + tig + 4]);
            #pragma unroll
            for (int nt = 0; nt < 4; nt++) {
                int col = nt * 8 + gid;
                unsigned b0 = __float_as_uint(sB[(ks + tig) * SB1_S + col]);
                unsigned b1 = __float_as_uint(sB[(ks + tig + 4) * SB1_S + col]);
                mma_tf32(acc[nt][0], acc[nt][1], acc[nt][2], acc[nt][3],
                         a0, a1, a2, a3, b0, b1);
            }
        }
        __syncthreads();
    }

    int r0 = brow + wid * 16 + gid;
    float as0 = 0, as1 = 0, ad0 = 0, ad1 = 0;
    #pragma unroll
    for (int nt = 0; nt < 4; nt++) {
        int col = nt * 8 + tig * 2;
        float av0 = a_src[col], av1 = a_src[col + 1];
        float dv0 = a_dst[col], dv1 = a_dst[col + 1];
        float d0 = acc[nt][0], d1 = acc[nt][1], d2 = acc[nt][2], d3 = acc[nt][3];
        as0 += d0 * av0 + d1 * av1;
        as1 += d2 * av0 + d3 * av1;
        ad0 += d0 * dv0 + d1 * dv1;
        ad1 += d2 * dv0 + d3 * dv1;
        if (r0 < NN)     *(float2*)(g_h1 + r0 * C1 + col)       = make_float2(d0, d1);
        if (r0 + 8 < NN) *(float2*)(g_h1 + (r0 + 8) * C1 + col) = make_float2(d2, d3);
    }
    #pragma unroll
    for (int off = 1; off <= 2; off <<= 1) {
        as0 += __shfl_xor_sync(0xffffffffu, as0, off);
        as1 += __shfl_xor_sync(0xffffffffu, as1, off);
        ad0 += __shfl_xor_sync(0xffffffffu, ad0, off);
        ad1 += __shfl_xor_sync(0xffffffffu, ad1, off);
    }
    if (tig == 0) {
        if (r0 < NN)     { g_as1[r0] = as0;     g_ad1[r0] = ad0; }
        if (r0 + 8 < NN) { g_as1[r0 + 8] = as1; g_ad1[r0 + 8] = ad1; }
    }
}

// ---------------- L6: agg1 + b1 + block-reduced colsum + fused predict (last block) ----------------
__global__ void agg1_pred(float* __restrict__ emb, const float* __restrict__ b1,
                          const float* __restrict__ hW1, const float* __restrict__ hb1,
                          const float* __restrict__ hW2, const float* __restrict__ hb2,
                          float* __restrict__ out, int pred_idx) {
    __shared__ float sred[256];
    __shared__ unsigned s_ticket;
    int tid = threadIdx.x;
    int n = (blockIdx.x * blockDim.x + tid) >> 5;
    int lane = tid & 31;
    int beg = g_ptr[n], end = g_ptr[n + 1];
    float adn = g_ad1[n];

    float sum = 0.0f, acc = 0.0f;
    for (int i = beg; i < end; i++) {
        int s = g_csr_src[i];
        float wv = __expf(leaky(g_as1[s] + adn));
        sum += wv;
        acc += g_h1[s * C1 + lane] * wv;
    }
    float val = acc / sum + b1[lane];
    emb[n * C1 + lane] = val;

    sred[tid] = val;
    __syncthreads();
    if (tid < 32) {
        float t = sred[tid];
        #pragma unroll
        for (int r = 1; r < 8; r++) t += sred[r * 32 + tid];
        atomicAdd(&g_gsum[tid], t);
    }
    __threadfence();
    if (tid == 0) s_ticket = atomicAdd(&g_done, 1u);
    __syncthreads();
    if (s_ticket != gridDim.x - 1) return;

    __shared__ float ge[C1];
    __shared__ float red[64];
    if (tid < C1) ge[tid] = g_gsum[tid] * (1.0f / (float)NN);
    __syncthreads();
    if (tid < 64) {
        float s = hb1[tid];
        #pragma unroll
        for (int c = 0; c < C1; c++) s += ge[c] * hW1[c * 64 + tid];
        red[tid] = fmaxf(s, 0.0f) * hW2[tid];
    }
    __syncthreads();
    if (tid == 0) {
        float t = 0.0f;
        #pragma unroll
        for (int i = 0; i < 64; i++) t += red[i];
        out[pred_idx] = t + hb2[0];
        g_done = 0;
    }
    if (tid < C1) g_gsum[tid] = 0.0f;
}

// ---------------- launch ----------------
extern "C" void kernel_launch(void* const* d_in, const int* in_sizes, int n_in,
                              void* d_out, int out_size) {
    const float* x       = (const float*)d_in[0];
    const int*   ei      = (const int*)d_in[1];
    const float* W0      = (const float*)d_in[2];
    const float* a_src0  = (const float*)d_in[3];
    const float* a_dst0  = (const float*)d_in[4];
    const float* b0      = (const float*)d_in[5];
    const float* bn_g    = (const float*)d_in[6];
    const float* bn_b    = (const float*)d_in[7];
    const float* bn_m    = (const float*)d_in[8];
    const float* bn_v    = (const float*)d_in[9];
    const float* W1      = (const float*)d_in[10];
    const float* a_src1  = (const float*)d_in[11];
    const float* a_dst1  = (const float*)d_in[12];
    const float* b1      = (const float*)d_in[13];
    const float* hW1     = (const float*)d_in[14];
    const float* hb1     = (const float*)d_in[15];
    const float* hW2     = (const float*)d_in[16];
    const float* hb2     = (const float*)d_in[17];
    float* out = (float*)d_out;

    gemm0a_hist_kernel<<<HBLK + NA * 4, 256>>>(x, W0, a_src0, a_dst0, ei);
    scan_kernel<<<1, 1024>>>();
    gemm0b_scatter_kernel<<<NB * 4 + SCB, 256>>>(x, W0, a_src0, a_dst0, ei);
    agg0_csr<<<(NN * 32 + 255) / 256, 256>>>(b0, bn_g, bn_b, bn_m, bn_v);
    {
        dim3 grid(1, (NN + 127) / 128);
        gemm1_kernel<<<grid, 256>>>(W1, a_src1, a_dst1);
    }
    agg1_pred<<<(NN + 7) / 8, 256>>>(out, b1, hW1, hb1, hW2, hb2, out, out_size - 1);
}